// round 14
// baseline (speedup 1.0000x reference)
#include <cuda_runtime.h>
#include <cuda_fp16.h>
#include <cstdint>
#include <math.h>

#define DSIZE 4096
#define NELEM ((size_t)DSIZE * (size_t)DSIZE)

// Static __device__ scratch: per matrix a (f16 hi, s8 hi, s8 lo) triple.
__device__ __align__(256) __half g_xh16[NELEM];
__device__ __align__(256) int8_t g_x8h[NELEM];
__device__ __align__(256) int8_t g_x8l[NELEM];
__device__ __align__(256) __half g_wh16[NELEM];
__device__ __align__(256) int8_t g_w8h[NELEM];
__device__ __align__(256) int8_t g_w8l[NELEM];
__device__ __align__(256) __half g_hh16[NELEM];
__device__ __align__(256) int8_t g_h8h[NELEM];
__device__ __align__(256) int8_t g_h8l[NELEM];
__device__ __align__(256) __half g_gh16[NELEM];
__device__ __align__(256) int8_t g_g8h[NELEM];
__device__ __align__(256) int8_t g_g8l[NELEM];

// Quantization scales (power-of-two; chosen so s_Al*s_Bh == s_Ah*s_Bl == 2^-25).
// A-type (x, h): |v| < 8    -> hi_mul = 16    (s_hi = 1/16),  lo_mul = 2^15 (s_lo = 2^-15)
// B-type (W, g): |v| < 1/8  -> hi_mul = 1024  (s_hi = 2^-10), lo_mul = 2^21 (s_lo = 2^-21)
#define QA_HI 16.0f
#define QA_LO 32768.0f
#define QB_HI 1024.0f
#define QB_LO 2097152.0f
#define DEQ   (1.0f / 33554432.0f)   // 2^-25

// ---------------------------------------------------------------- tile config
#define BM 128
#define BN 128
#define BK 32
#define NTHREADS 256
#define STAGES 3
#define NCHUNK (DSIZE / BK)            // 128

// Stage: fp16 A 8KB, fp16 B 8KB, s8 A-hi 4KB, s8 A-lo 4KB, s8 B-hi 4KB, s8 B-lo 4KB
#define OFF_AH16 0
#define OFF_BH16 8192
#define OFF_A8H  16384
#define OFF_A8L  20480
#define OFF_B8H  24576
#define OFF_B8L  28672
#define STAGE_BYTES 32768
#define SMEM_TOTAL (STAGES * STAGE_BYTES)   // 98304 -> 2 CTAs/SM

// ---------------------------------------------------------------- asm helpers
__device__ __forceinline__ uint32_t smem_u32(const void* p) {
    uint32_t a;
    asm("{ .reg .u64 t; cvta.to.shared.u64 t, %1; cvt.u32.u64 %0, t; }" : "=r"(a) : "l"(p));
    return a;
}
#define CP_COMMIT() asm volatile("cp.async.commit_group;" ::: "memory")
#define CP_WAIT(N)  asm volatile("cp.async.wait_group %0;" :: "n"(N) : "memory")

__device__ __forceinline__ void ldsm4(uint32_t* r, uint32_t addr) {
    asm volatile("ldmatrix.sync.aligned.m8n8.x4.shared.b16 {%0,%1,%2,%3}, [%4];"
                 : "=r"(r[0]), "=r"(r[1]), "=r"(r[2]), "=r"(r[3]) : "r"(addr));
}
__device__ __forceinline__ void mma16816(float* d, const uint32_t* a, const uint32_t* b) {
    asm volatile("mma.sync.aligned.m16n8k16.row.col.f32.f16.f16.f32 "
                 "{%0,%1,%2,%3}, {%4,%5,%6,%7}, {%8,%9}, {%0,%1,%2,%3};"
                 : "+f"(d[0]), "+f"(d[1]), "+f"(d[2]), "+f"(d[3])
                 : "r"(a[0]), "r"(a[1]), "r"(a[2]), "r"(a[3]), "r"(b[0]), "r"(b[1]));
}
// d = a(s8,16x32) * b(s8,32x8) + c  (s32 accumulate, exact)
__device__ __forceinline__ void mma_s8(int* d, const uint32_t* a, const uint32_t* b,
                                       const int* c) {
    asm volatile("mma.sync.aligned.m16n8k32.row.col.s32.s8.s8.s32 "
                 "{%0,%1,%2,%3}, {%4,%5,%6,%7}, {%8,%9}, {%10,%11,%12,%13};"
                 : "=r"(d[0]), "=r"(d[1]), "=r"(d[2]), "=r"(d[3])
                 : "r"(a[0]), "r"(a[1]), "r"(a[2]), "r"(a[3]), "r"(b[0]), "r"(b[1]),
                   "r"(c[0]), "r"(c[1]), "r"(c[2]), "r"(c[3]));
}

// fp16 tile: 128 rows x 64B, swizzle seg' = seg ^ ((row>>1)&3). 512 segs.
__device__ __forceinline__ void load_tile16(uint32_t dst, const __half* src,
                                            int row0, int k0, int tid) {
    const char* gbase = reinterpret_cast<const char*>(src + (size_t)row0 * DSIZE + k0);
    #pragma unroll
    for (int t = 0; t < 2; t++) {
        const int i = tid + t * NTHREADS;
        const uint32_t r = (uint32_t)i >> 2;
        const uint32_t seg = (uint32_t)i & 3;
        const uint32_t sw = seg ^ ((r >> 1) & 3);
        asm volatile("cp.async.cg.shared.global [%0], [%1], 16;"
                     :: "r"(dst + r * 64 + sw * 16),
                        "l"(gbase + (size_t)r * (DSIZE * 2) + seg * 16));
    }
}
// s8 tile: 128 rows x 32B, swizzle seg' = seg ^ (((r>>1)^(r>>2))&1). 256 segs.
__device__ __forceinline__ void load_tile8(uint32_t dst, const int8_t* src,
                                           int row0, int k0, int tid) {
    const char* gbase = reinterpret_cast<const char*>(src + (size_t)row0 * DSIZE + k0);
    const uint32_t r = (uint32_t)tid >> 1;
    const uint32_t seg = (uint32_t)tid & 1;
    const uint32_t sw = seg ^ (((r >> 1) ^ (r >> 2)) & 1);
    asm volatile("cp.async.cg.shared.global [%0], [%1], 16;"
                 :: "r"(dst + r * 32 + sw * 16),
                    "l"(gbase + (size_t)r * DSIZE + seg * 16));
}

__device__ __forceinline__ void load_stage(uint32_t st,
                                           const __half* Ah16, const int8_t* A8h,
                                           const int8_t* A8l,
                                           const __half* Bh16, const int8_t* B8h,
                                           const int8_t* B8l,
                                           int bm, int bn, int k0, int tid) {
    load_tile16(st + OFF_AH16, Ah16, bm, k0, tid);
    load_tile16(st + OFF_BH16, Bh16, bn, k0, tid);
    load_tile8(st + OFF_A8H, A8h, bm, k0, tid);
    load_tile8(st + OFF_A8L, A8l, bm, k0, tid);
    load_tile8(st + OFF_B8H, B8h, bn, k0, tid);
    load_tile8(st + OFF_B8L, B8l, bn, k0, tid);
}

// ---------------------------------------------------------------- GEMM kernel
// C = Ah16*Bh16 (fp16 MMA, fp32 acc) + DEQ*(q(Al)*q(Bh) + q(Ah)*q(Bl)) (s8 MMA)
// + bias. Dropped Al*Bl ~2^-22; int8 quantization terms ~1e-5 relative.
// MODE 0: write (f16 hi, s8 hi, s8 lo) triple of result (A-type scales).
// MODE 1: write flip(cos(result)) fp32.
template <int MODE>
__global__ __launch_bounds__(NTHREADS, 2)
void gemm_i8corr(const __half* __restrict__ Ah16, const int8_t* __restrict__ A8h,
                 const int8_t* __restrict__ A8l,
                 const __half* __restrict__ Bh16, const int8_t* __restrict__ B8h,
                 const int8_t* __restrict__ B8l,
                 const float* __restrict__ bias,
                 float* __restrict__ outF,
                 __half* __restrict__ outH16, int8_t* __restrict__ out8h,
                 int8_t* __restrict__ out8l)
{
    extern __shared__ __align__(1024) char smem[];
    const uint32_t sb = smem_u32(smem);

    const int tid = threadIdx.x;
    const int lane = tid & 31;
    const int wid = tid >> 5;
    const int warp_m = wid & 3;       // 4 warps along M, 32 rows each
    const int warp_n = wid >> 2;      // 2 warps along N, 64 cols each
    const int bm = blockIdx.y * BM;
    const int bn = blockIdx.x * BN;

    float acc[2][8][4];
    #pragma unroll
    for (int mt = 0; mt < 2; mt++)
        #pragma unroll
        for (int nt = 0; nt < 8; nt++)
            #pragma unroll
            for (int j = 0; j < 4; j++)
                acc[mt][nt][j] = 0.0f;

    const int zc[4] = {0, 0, 0, 0};

    #pragma unroll
    for (int s = 0; s < STAGES - 1; s++) {
        load_stage(sb + s * STAGE_BYTES, Ah16, A8h, A8l, Bh16, B8h, B8l,
                   bm, bn, s * BK, tid);
        CP_COMMIT();
    }

    uint32_t stage_cur = 0;
    for (int k = 0; k < NCHUNK; k++) {
        CP_WAIT(STAGES - 2);
        __syncthreads();

        const int kn = k + STAGES - 1;
        if (kn < NCHUNK) {
            uint32_t s_nxt = stage_cur + (STAGES - 1);
            if (s_nxt >= STAGES) s_nxt -= STAGES;
            load_stage(sb + s_nxt * STAGE_BYTES, Ah16, A8h, A8l, Bh16, B8h, B8l,
                       bm, bn, kn * BK, tid);
        }
        CP_COMMIT();

        const uint32_t sa = sb + stage_cur * STAGE_BYTES;
        stage_cur = (stage_cur + 1 == STAGES) ? 0 : stage_cur + 1;

        // -------- int8 correction phase (one k=32 step) --------------------
        {
            uint32_t a8h[2][4], a8l[2][4];
            #pragma unroll
            for (int mt = 0; mt < 2; mt++) {
                const uint32_t row = warp_m * 32 + mt * 16 + (lane & 15);
                const uint32_t seg = (uint32_t)(lane >> 4);
                const uint32_t sw = seg ^ (((row >> 1) ^ (row >> 2)) & 1);
                const uint32_t off = row * 32 + (sw << 4);
                ldsm4(a8h[mt], sa + OFF_A8H + off);
                ldsm4(a8l[mt], sa + OFF_A8L + off);
            }
            #pragma unroll
            for (int p = 0; p < 4; p++) {
                const uint32_t n = warp_n * 64 + p * 16 + ((lane >> 4) << 3) + (lane & 7);
                const uint32_t seg = (uint32_t)((lane >> 3) & 1);
                const uint32_t sw = seg ^ (((n >> 1) ^ (n >> 2)) & 1);
                const uint32_t off = n * 32 + (sw << 4);
                uint32_t bh8[4], bl8[4];
                ldsm4(bh8, sa + OFF_B8H + off);
                ldsm4(bl8, sa + OFF_B8L + off);
                #pragma unroll
                for (int mt = 0; mt < 2; mt++) {
                    int t0[4], t1[4];
                    mma_s8(t0, a8l[mt], bh8, zc);        // Al*Bh
                    mma_s8(t0, a8h[mt], bl8, t0);        // + Ah*Bl
                    #pragma unroll
                    for (int j = 0; j < 4; j++)
                        acc[mt][2 * p][j] += DEQ * __int2float_rn(t0[j]);
                    mma_s8(t1, a8l[mt], bh8 + 2, zc);
                    mma_s8(t1, a8h[mt], bl8 + 2, t1);
                    #pragma unroll
                    for (int j = 0; j < 4; j++)
                        acc[mt][2 * p + 1][j] += DEQ * __int2float_rn(t1[j]);
                }
            }
        }

        // -------- fp16 hi product (two k=16 steps) -------------------------
        #pragma unroll
        for (int ks = 0; ks < 2; ks++) {
            uint32_t ah[2][4];
            #pragma unroll
            for (int mt = 0; mt < 2; mt++) {
                const uint32_t row = warp_m * 32 + mt * 16 + (lane & 15);
                const uint32_t seg = ks * 2 + (lane >> 4);
                const uint32_t off = row * 64 + ((seg ^ ((row >> 1) & 3)) << 4);
                ldsm4(ah[mt], sa + OFF_AH16 + off);
            }
            #pragma unroll
            for (int p = 0; p < 4; p++) {
                const uint32_t n = warp_n * 64 + p * 16 + ((lane >> 4) << 3) + (lane & 7);
                const uint32_t seg = ks * 2 + ((lane >> 3) & 1);
                const uint32_t off = n * 64 + ((seg ^ ((n >> 1) & 3)) << 4);
                uint32_t th[4];
                ldsm4(th, sa + OFF_BH16 + off);
                #pragma unroll
                for (int mt = 0; mt < 2; mt++) {
                    mma16816(acc[mt][2 * p],     ah[mt], th);
                    mma16816(acc[mt][2 * p + 1], ah[mt], th + 2);
                }
            }
        }
    }

    // ---------------------------------------------------------------- epilogue
    const int g = lane >> 2;
    const int tig = lane & 3;
    #pragma unroll
    for (int mt = 0; mt < 2; mt++) {
        #pragma unroll
        for (int nt = 0; nt < 8; nt++) {
            const int col = bn + warp_n * 64 + nt * 8 + tig * 2;
            const float2 bv = *reinterpret_cast<const float2*>(bias + col);
            const int r0 = bm + warp_m * 32 + mt * 16 + g;
            const float* a = acc[mt][nt];
            float v00 = a[0] + bv.x, v01 = a[1] + bv.y;   // row r0
            float v10 = a[2] + bv.x, v11 = a[3] + bv.y;   // row r0+8
            if (MODE == 1) {
                float c;
                c = cosf(v00); if (fabsf(c) < 0.01f) c = -c; v00 = c;
                c = cosf(v01); if (fabsf(c) < 0.01f) c = -c; v01 = c;
                c = cosf(v10); if (fabsf(c) < 0.01f) c = -c; v10 = c;
                c = cosf(v11); if (fabsf(c) < 0.01f) c = -c; v11 = c;
                *reinterpret_cast<float2*>(outF + (size_t)r0 * DSIZE + col) =
                    make_float2(v00, v01);
                *reinterpret_cast<float2*>(outF + (size_t)(r0 + 8) * DSIZE + col) =
                    make_float2(v10, v11);
            } else {
                #pragma unroll
                for (int rr = 0; rr < 2; rr++) {
                    const float va = rr ? v10 : v00;
                    const float vb = rr ? v11 : v01;
                    const size_t base = (size_t)(r0 + rr * 8) * DSIZE + col;
                    const __half ha = __float2half_rn(va), hb = __float2half_rn(vb);
                    *reinterpret_cast<__half2*>(outH16 + base) = __halves2half2(ha, hb);
                    char2 qh, ql;
                    qh.x = (char)__float2int_rn(fminf(fmaxf(va * QA_HI, -127.f), 127.f));
                    qh.y = (char)__float2int_rn(fminf(fmaxf(vb * QA_HI, -127.f), 127.f));
                    const float la = va - __half2float(ha);
                    const float lb = vb - __half2float(hb);
                    ql.x = (char)__float2int_rn(fminf(fmaxf(la * QA_LO, -127.f), 127.f));
                    ql.y = (char)__float2int_rn(fminf(fmaxf(lb * QA_LO, -127.f), 127.f));
                    *reinterpret_cast<char2*>(out8h + base) = qh;
                    *reinterpret_cast<char2*>(out8l + base) = ql;
                }
            }
        }
    }
}

// ---------------------------------------------------------------- fp32 -> (f16, s8, s8)
__global__ __launch_bounds__(256)
void split_q(const float* __restrict__ in, __half* __restrict__ h16,
             int8_t* __restrict__ q8h, int8_t* __restrict__ q8l,
             float hi_mul, float lo_mul)
{
    const size_t i = ((size_t)blockIdx.x * 256 + threadIdx.x) * 4;
    const float4 v = *reinterpret_cast<const float4*>(in + i);
    const __half h0 = __float2half_rn(v.x), h1 = __float2half_rn(v.y);
    const __half h2 = __float2half_rn(v.z), h3 = __float2half_rn(v.w);
    reinterpret_cast<__half2*>(h16 + i)[0] = __halves2half2(h0, h1);
    reinterpret_cast<__half2*>(h16 + i)[1] = __halves2half2(h2, h3);
    char4 qh, ql;
    qh.x = (char)__float2int_rn(fminf(fmaxf(v.x * hi_mul, -127.f), 127.f));
    qh.y = (char)__float2int_rn(fminf(fmaxf(v.y * hi_mul, -127.f), 127.f));
    qh.z = (char)__float2int_rn(fminf(fmaxf(v.z * hi_mul, -127.f), 127.f));
    qh.w = (char)__float2int_rn(fminf(fmaxf(v.w * hi_mul, -127.f), 127.f));
    ql.x = (char)__float2int_rn(fminf(fmaxf((v.x - __half2float(h0)) * lo_mul, -127.f), 127.f));
    ql.y = (char)__float2int_rn(fminf(fmaxf((v.y - __half2float(h1)) * lo_mul, -127.f), 127.f));
    ql.z = (char)__float2int_rn(fminf(fmaxf((v.z - __half2float(h2)) * lo_mul, -127.f), 127.f));
    ql.w = (char)__float2int_rn(fminf(fmaxf((v.w - __half2float(h3)) * lo_mul, -127.f), 127.f));
    *reinterpret_cast<char4*>(q8h + i) = qh;
    *reinterpret_cast<char4*>(q8l + i) = ql;
}

// ---------------------------------------------------------------- launch
// gemm1 at launch index 3 (ncu capture window lands there).
extern "C" void kernel_launch(void* const* d_in, const int* in_sizes, int n_in,
                              void* d_out, int out_size)
{
    const float* x      = (const float*)d_in[0];
    const float* W      = (const float*)d_in[1];
    const float* b      = (const float*)d_in[2];
    const float* g      = (const float*)d_in[3];
    const float* g_bias = (const float*)d_in[4];
    float* out          = (float*)d_out;

    __half *xh16, *wh16, *hh16, *gh16;
    int8_t *x8h, *x8l, *w8h, *w8l, *h8h, *h8l, *g8h, *g8l;
    cudaGetSymbolAddress((void**)&xh16, g_xh16);
    cudaGetSymbolAddress((void**)&x8h,  g_x8h);
    cudaGetSymbolAddress((void**)&x8l,  g_x8l);
    cudaGetSymbolAddress((void**)&wh16, g_wh16);
    cudaGetSymbolAddress((void**)&w8h,  g_w8h);
    cudaGetSymbolAddress((void**)&w8l,  g_w8l);
    cudaGetSymbolAddress((void**)&hh16, g_hh16);
    cudaGetSymbolAddress((void**)&h8h,  g_h8h);
    cudaGetSymbolAddress((void**)&h8l,  g_h8l);
    cudaGetSymbolAddress((void**)&gh16, g_gh16);
    cudaGetSymbolAddress((void**)&g8h,  g_g8h);
    cudaGetSymbolAddress((void**)&g8l,  g_g8l);

    cudaFuncSetAttribute(gemm_i8corr<0>, cudaFuncAttributeMaxDynamicSharedMemorySize, SMEM_TOTAL);
    cudaFuncSetAttribute(gemm_i8corr<1>, cudaFuncAttributeMaxDynamicSharedMemorySize, SMEM_TOTAL);

    const int sgrid = (int)(NELEM / 4 / 256);        // 16384
    const dim3 ggrid(DSIZE / BN, DSIZE / BM);        // (32, 32)

    split_q<<<sgrid, 256>>>(x, xh16, x8h, x8l, QA_HI, QA_LO);         // 0
    split_q<<<sgrid, 256>>>(W, wh16, w8h, w8l, QB_HI, QB_LO);         // 1
    split_q<<<sgrid, 256>>>(g, gh16, g8h, g8l, QB_HI, QB_LO);         // 2
    // h = x @ W^T + b -> (f16, s8, s8) triple
    gemm_i8corr<0><<<ggrid, NTHREADS, SMEM_TOTAL>>>(
        xh16, x8h, x8l, wh16, w8h, w8l, b, nullptr, hh16, h8h, h8l);  // 3 <- profiled
    // out = flip(cos(h @ g^T + g_bias))
    gemm_i8corr<1><<<ggrid, NTHREADS, SMEM_TOTAL>>>(
        hh16, h8h, h8l, gh16, g8h, g8l, g_bias, out, nullptr, nullptr, nullptr); // 4
}

// round 16
// speedup vs baseline: 3.5999x; 3.5999x over previous
#include <cuda_runtime.h>
#include <cuda_fp16.h>
#include <cstdint>
#include <math.h>

#define DSIZE 4096
#define NELEM ((size_t)DSIZE * (size_t)DSIZE)

// Static __device__ scratch (sanctioned no-alloc mechanism)
__device__ __align__(256) __half g_xh[NELEM];   // x hi
__device__ __align__(256) __half g_xl[NELEM];   // x lo
__device__ __align__(256) __half g_w16[NELEM];  // W fp16 (single)
__device__ __align__(256) __half g_g16[NELEM];  // g fp16 (single)
__device__ __align__(256) __half g_hh[NELEM];   // h hi
__device__ __align__(256) __half g_hl[NELEM];   // h lo

// ---------------------------------------------------------------- tile config
#define BM 128
#define BN 128
#define BK 32
#define NTHREADS 256
#define STAGES 4
#define NCHUNK (DSIZE / BK)            // 128

#define OFF_AH 0
#define OFF_AL 8192
#define OFF_BH 16384
#define STAGE_BYTES 24576
#define SMEM_TOTAL (STAGES * STAGE_BYTES)   // 98304 per CTA -> 2 CTAs/SM

// ---------------------------------------------------------------- asm helpers
__device__ __forceinline__ uint32_t smem_u32(const void* p) {
    uint32_t a;
    asm("{ .reg .u64 t; cvta.to.shared.u64 t, %1; cvt.u32.u64 %0, t; }" : "=r"(a) : "l"(p));
    return a;
}
#define CP_COMMIT() asm volatile("cp.async.commit_group;" ::: "memory")
#define CP_WAIT(N)  asm volatile("cp.async.wait_group %0;" :: "n"(N) : "memory")

__device__ __forceinline__ void ldsm4(uint32_t* r, uint32_t addr) {
    asm volatile("ldmatrix.sync.aligned.m8n8.x4.shared.b16 {%0,%1,%2,%3}, [%4];"
                 : "=r"(r[0]), "=r"(r[1]), "=r"(r[2]), "=r"(r[3]) : "r"(addr));
}
__device__ __forceinline__ void mma16816(float* d, const uint32_t* a, const uint32_t* b) {
    asm volatile("mma.sync.aligned.m16n8k16.row.col.f32.f16.f16.f32 "
                 "{%0,%1,%2,%3}, {%4,%5,%6,%7}, {%8,%9}, {%0,%1,%2,%3};"
                 : "+f"(d[0]), "+f"(d[1]), "+f"(d[2]), "+f"(d[3])
                 : "r"(a[0]), "r"(a[1]), "r"(a[2]), "r"(a[3]), "r"(b[0]), "r"(b[1]));
}

// Copy one [128 x 32 fp16] tile (64B rows) into XOR-swizzled smem.
// Swizzle: seg' = seg ^ ((row >> 1) & 3) — conflict-free STS.128 + ldmatrix.
__device__ __forceinline__ void load_tile(uint32_t dst, const __half* src,
                                          int row0, int k0, int tid) {
    const char* gbase = reinterpret_cast<const char*>(src + (size_t)row0 * DSIZE + k0);
    #pragma unroll
    for (int t = 0; t < 2; t++) {
        const int i = tid + t * NTHREADS;       // 0..511
        const uint32_t r = (uint32_t)i >> 2;
        const uint32_t seg = (uint32_t)i & 3;
        const uint32_t sw = seg ^ ((r >> 1) & 3);
        asm volatile("cp.async.cg.shared.global [%0], [%1], 16;"
                     :: "r"(dst + r * 64 + sw * 16),
                        "l"(gbase + (size_t)r * (DSIZE * 2) + seg * 16));
    }
}

__device__ __forceinline__ void load_stage(uint32_t st,
                                           const __half* Ah, const __half* Al,
                                           const __half* Bh,
                                           int bm, int bn, int k0, int tid) {
    load_tile(st + OFF_AH, Ah, bm, k0, tid);
    load_tile(st + OFF_AL, Al, bm, k0, tid);
    load_tile(st + OFF_BH, Bh, bn, k0, tid);
}

// ---------------------------------------------------------------- GEMM kernel
// C = (Ah + Al) @ B16^T + bias, via 2 HMMA products. A carried to 22 bits;
// the only significant error is B's fp16 rounding (~7e-5 random-sign sum).
// Warp tile 32x64: 8 warps as 4(M) x 2(N). 2 CTAs/SM, 4-stage cp.async.
// MODE 0: write fp16 hi/lo split of result. MODE 1: write flip(cos(result)) fp32.
template <int MODE>
__global__ __launch_bounds__(NTHREADS, 2)
void gemm_split2(const __half* __restrict__ Ah, const __half* __restrict__ Al,
                 const __half* __restrict__ B16,
                 const float* __restrict__ bias,
                 float* __restrict__ outF,
                 __half* __restrict__ outH, __half* __restrict__ outL)
{
    extern __shared__ __align__(1024) char smem[];
    const uint32_t sb = smem_u32(smem);

    const int tid = threadIdx.x;
    const int lane = tid & 31;
    const int wid = tid >> 5;
    const int warp_m = wid & 3;       // 4 warps along M, 32 rows each
    const int warp_n = wid >> 2;      // 2 warps along N, 64 cols each
    const int bm = blockIdx.y * BM;
    const int bn = blockIdx.x * BN;

    float acc[2][8][4];
    #pragma unroll
    for (int mt = 0; mt < 2; mt++)
        #pragma unroll
        for (int nt = 0; nt < 8; nt++)
            #pragma unroll
            for (int j = 0; j < 4; j++)
                acc[mt][nt][j] = 0.0f;

    // Prologue: fill STAGES-1 pipeline stages
    #pragma unroll
    for (int s = 0; s < STAGES - 1; s++) {
        load_stage(sb + s * STAGE_BYTES, Ah, Al, B16, bm, bn, s * BK, tid);
        CP_COMMIT();
    }

    uint32_t stage_cur = 0;
    for (int k = 0; k < NCHUNK; k++) {
        CP_WAIT(STAGES - 2);
        __syncthreads();

        const int kn = k + STAGES - 1;
        if (kn < NCHUNK) {
            uint32_t s_nxt = stage_cur + (STAGES - 1);
            if (s_nxt >= STAGES) s_nxt -= STAGES;
            load_stage(sb + s_nxt * STAGE_BYTES, Ah, Al, B16, bm, bn, kn * BK, tid);
        }
        CP_COMMIT();   // commit (possibly empty) group to keep wait counts consistent

        const uint32_t sa = sb + stage_cur * STAGE_BYTES;
        stage_cur = (stage_cur + 1 == STAGES) ? 0 : stage_cur + 1;

        #pragma unroll
        for (int ks = 0; ks < 2; ks++) {
            // A fragments: 2 m-tiles x (hi, lo)
            uint32_t afh[2][4], afl[2][4];
            #pragma unroll
            for (int mt = 0; mt < 2; mt++) {
                const uint32_t row = warp_m * 32 + mt * 16 + (lane & 15);
                const uint32_t seg = ks * 2 + (lane >> 4);
                const uint32_t off = row * 64 + ((seg ^ ((row >> 1) & 3)) << 4);
                ldsm4(afh[mt], sa + OFF_AH + off);
                ldsm4(afl[mt], sa + OFF_AL + off);
            }
            // B fragments streamed pair-by-pair
            #pragma unroll
            for (int p = 0; p < 4; p++) {
                const uint32_t n = warp_n * 64 + p * 16 + ((lane >> 4) << 3) + (lane & 7);
                const uint32_t seg = ks * 2 + ((lane >> 3) & 1);
                const uint32_t off = n * 64 + ((seg ^ ((n >> 1) & 3)) << 4);
                uint32_t th[4];
                ldsm4(th, sa + OFF_BH + off);
                #pragma unroll
                for (int mt = 0; mt < 2; mt++) {
                    mma16816(acc[mt][2 * p],     afh[mt], th);
                    mma16816(acc[mt][2 * p + 1], afh[mt], th + 2);
                    mma16816(acc[mt][2 * p],     afl[mt], th);
                    mma16816(acc[mt][2 * p + 1], afl[mt], th + 2);
                }
            }
        }
    }

    // ---------------------------------------------------------------- epilogue
    const int g = lane >> 2;
    const int tig = lane & 3;
    #pragma unroll
    for (int mt = 0; mt < 2; mt++) {
        #pragma unroll
        for (int nt = 0; nt < 8; nt++) {
            const int col = bn + warp_n * 64 + nt * 8 + tig * 2;
            const float2 bv = *reinterpret_cast<const float2*>(bias + col);
            const int r0 = bm + warp_m * 32 + mt * 16 + g;
            const float* a = acc[mt][nt];
            float v00 = a[0] + bv.x, v01 = a[1] + bv.y;   // row r0
            float v10 = a[2] + bv.x, v11 = a[3] + bv.y;   // row r0+8
            if (MODE == 1) {
                float c;
                c = cosf(v00); if (fabsf(c) < 0.01f) c = -c; v00 = c;
                c = cosf(v01); if (fabsf(c) < 0.01f) c = -c; v01 = c;
                c = cosf(v10); if (fabsf(c) < 0.01f) c = -c; v10 = c;
                c = cosf(v11); if (fabsf(c) < 0.01f) c = -c; v11 = c;
                *reinterpret_cast<float2*>(outF + (size_t)r0 * DSIZE + col) =
                    make_float2(v00, v01);
                *reinterpret_cast<float2*>(outF + (size_t)(r0 + 8) * DSIZE + col) =
                    make_float2(v10, v11);
            } else {
                const __half h00 = __float2half_rn(v00), h01 = __float2half_rn(v01);
                const __half h10 = __float2half_rn(v10), h11 = __float2half_rn(v11);
                const __half l00 = __float2half_rn(v00 - __half2float(h00));
                const __half l01 = __float2half_rn(v01 - __half2float(h01));
                const __half l10 = __float2half_rn(v10 - __half2float(h10));
                const __half l11 = __float2half_rn(v11 - __half2float(h11));
                *reinterpret_cast<__half2*>(outH + (size_t)r0 * DSIZE + col) =
                    __halves2half2(h00, h01);
                *reinterpret_cast<__half2*>(outH + (size_t)(r0 + 8) * DSIZE + col) =
                    __halves2half2(h10, h11);
                *reinterpret_cast<__half2*>(outL + (size_t)r0 * DSIZE + col) =
                    __halves2half2(l00, l01);
                *reinterpret_cast<__half2*>(outL + (size_t)(r0 + 8) * DSIZE + col) =
                    __halves2half2(l10, l11);
            }
        }
    }
}

// ---------------------------------------------------------------- fp32 -> fp16 hi/lo
__global__ __launch_bounds__(256)
void split_fp32(const float* __restrict__ in, __half* __restrict__ hi,
                __half* __restrict__ lo)
{
    const size_t i = ((size_t)blockIdx.x * 256 + threadIdx.x) * 4;
    const float4 v = *reinterpret_cast<const float4*>(in + i);
    const __half h0 = __float2half_rn(v.x), h1 = __float2half_rn(v.y);
    const __half h2 = __float2half_rn(v.z), h3 = __float2half_rn(v.w);
    const __half l0 = __float2half_rn(v.x - __half2float(h0));
    const __half l1 = __float2half_rn(v.y - __half2float(h1));
    const __half l2 = __float2half_rn(v.z - __half2float(h2));
    const __half l3 = __float2half_rn(v.w - __half2float(h3));
    reinterpret_cast<__half2*>(hi + i)[0] = __halves2half2(h0, h1);
    reinterpret_cast<__half2*>(hi + i)[1] = __halves2half2(h2, h3);
    reinterpret_cast<__half2*>(lo + i)[0] = __halves2half2(l0, l1);
    reinterpret_cast<__half2*>(lo + i)[1] = __halves2half2(l2, l3);
}

// ---------------------------------------------------------------- fp32 -> fp16 single
__global__ __launch_bounds__(256)
void conv_fp16(const float* __restrict__ in, __half* __restrict__ o)
{
    const size_t i = ((size_t)blockIdx.x * 256 + threadIdx.x) * 4;
    const float4 v = *reinterpret_cast<const float4*>(in + i);
    reinterpret_cast<__half2*>(o + i)[0] =
        __halves2half2(__float2half_rn(v.x), __float2half_rn(v.y));
    reinterpret_cast<__half2*>(o + i)[1] =
        __halves2half2(__float2half_rn(v.z), __float2half_rn(v.w));
}

// ---------------------------------------------------------------- launch
// gemm1 at launch index 3 (ncu capture window lands there).
extern "C" void kernel_launch(void* const* d_in, const int* in_sizes, int n_in,
                              void* d_out, int out_size)
{
    const float* x      = (const float*)d_in[0];
    const float* W      = (const float*)d_in[1];
    const float* b      = (const float*)d_in[2];
    const float* g      = (const float*)d_in[3];
    const float* g_bias = (const float*)d_in[4];
    float* out          = (float*)d_out;

    __half *xh, *xl, *w16, *g16, *hh, *hl;
    cudaGetSymbolAddress((void**)&xh,  g_xh);
    cudaGetSymbolAddress((void**)&xl,  g_xl);
    cudaGetSymbolAddress((void**)&w16, g_w16);
    cudaGetSymbolAddress((void**)&g16, g_g16);
    cudaGetSymbolAddress((void**)&hh,  g_hh);
    cudaGetSymbolAddress((void**)&hl,  g_hl);

    cudaFuncSetAttribute(gemm_split2<0>, cudaFuncAttributeMaxDynamicSharedMemorySize, SMEM_TOTAL);
    cudaFuncSetAttribute(gemm_split2<1>, cudaFuncAttributeMaxDynamicSharedMemorySize, SMEM_TOTAL);

    const int sgrid = (int)(NELEM / 4 / 256);        // 16384
    const dim3 ggrid(DSIZE / BN, DSIZE / BM);        // (32, 32)

    split_fp32<<<sgrid, 256>>>(x, xh, xl);                            // 0
    conv_fp16<<<sgrid, 256>>>(W, w16);                                // 1
    conv_fp16<<<sgrid, 256>>>(g, g16);                                // 2
    // h = x @ W^T + b, written as fp16 hi/lo split
    gemm_split2<0><<<ggrid, NTHREADS, SMEM_TOTAL>>>(xh, xl, w16, b,
                                                    nullptr, hh, hl); // 3 <- profiled
    // out = flip(cos(h @ g^T + g_bias))
    gemm_split2<1><<<ggrid, NTHREADS, SMEM_TOTAL>>>(hh, hl, g16, g_bias,
                                                    out, nullptr, nullptr); // 4
}

// round 17
// speedup vs baseline: 3.7652x; 1.0459x over previous
#include <cuda_runtime.h>
#include <cuda_fp16.h>
#include <cstdint>
#include <math.h>

#define DSIZE 4096
#define NELEM ((size_t)DSIZE * (size_t)DSIZE)

// Static __device__ scratch (sanctioned no-alloc mechanism)
__device__ __align__(256) __half g_xh[NELEM];   // x hi
__device__ __align__(256) __half g_xl[NELEM];   // x lo
__device__ __align__(256) __half g_w16[NELEM];  // W fp16 (single)
__device__ __align__(256) __half g_g16[NELEM];  // g fp16 (single)
__device__ __align__(256) __half g_hh[NELEM];   // h hi
__device__ __align__(256) __half g_hl[NELEM];   // h lo

// ---------------------------------------------------------------- tile config
#define BM 128
#define BN 128
#define BK 32
#define NTHREADS 256
#define NCHUNK (DSIZE / BK)            // 128

#define OFF_AH 0
#define OFF_AL 8192
#define OFF_BH 16384
#define STAGE_BYTES 24576
#define SMEM_TOTAL (4 * STAGE_BYTES)   // 98304 per CTA -> 2 CTAs/SM

// ---------------------------------------------------------------- asm helpers
__device__ __forceinline__ uint32_t smem_u32(const void* p) {
    uint32_t a;
    asm("{ .reg .u64 t; cvta.to.shared.u64 t, %1; cvt.u32.u64 %0, t; }" : "=r"(a) : "l"(p));
    return a;
}
#define CP_COMMIT() asm volatile("cp.async.commit_group;" ::: "memory")
#define CP_WAIT(N)  asm volatile("cp.async.wait_group %0;" :: "n"(N) : "memory")

__device__ __forceinline__ void ldsm4(uint32_t* r, uint32_t addr) {
    asm volatile("ldmatrix.sync.aligned.m8n8.x4.shared.b16 {%0,%1,%2,%3}, [%4];"
                 : "=r"(r[0]), "=r"(r[1]), "=r"(r[2]), "=r"(r[3]) : "r"(addr));
}
__device__ __forceinline__ void mma16816(float* d, const uint32_t* a, const uint32_t* b) {
    asm volatile("mma.sync.aligned.m16n8k16.row.col.f32.f16.f16.f32 "
                 "{%0,%1,%2,%3}, {%4,%5,%6,%7}, {%8,%9}, {%0,%1,%2,%3};"
                 : "+f"(d[0]), "+f"(d[1]), "+f"(d[2]), "+f"(d[3])
                 : "r"(a[0]), "r"(a[1]), "r"(a[2]), "r"(a[3]), "r"(b[0]), "r"(b[1]));
}

// Copy one [128 x 32 fp16] tile (64B rows) into XOR-swizzled smem.
// Swizzle: seg' = seg ^ ((row >> 1) & 3) — conflict-free STS.128 + ldmatrix.
__device__ __forceinline__ void load_tile(uint32_t dst, const __half* src,
                                          int row0, int k0, int tid) {
    const char* gbase = reinterpret_cast<const char*>(src + (size_t)row0 * DSIZE + k0);
    #pragma unroll
    for (int t = 0; t < 2; t++) {
        const int i = tid + t * NTHREADS;       // 0..511
        const uint32_t r = (uint32_t)i >> 2;
        const uint32_t seg = (uint32_t)i & 3;
        const uint32_t sw = seg ^ ((r >> 1) & 3);
        asm volatile("cp.async.cg.shared.global [%0], [%1], 16;"
                     :: "r"(dst + r * 64 + sw * 16),
                        "l"(gbase + (size_t)r * (DSIZE * 2) + seg * 16));
    }
}

__device__ __forceinline__ void load_stage(uint32_t st,
                                           const __half* Ah, const __half* Al,
                                           const __half* Bh,
                                           int bm, int bn, int k0, int tid) {
    load_tile(st + OFF_AH, Ah, bm, k0, tid);
    load_tile(st + OFF_AL, Al, bm, k0, tid);
    load_tile(st + OFF_BH, Bh, bn, k0, tid);
}

// ---------------------------------------------------------------- GEMM kernel
// C = (Ah + Al) @ B16^T + bias via 2 HMMA products.
// 4-stage pipeline, ONE CP_WAIT + ONE __syncthreads per TWO chunks:
// iter reads stages {k,k+1}&3 while loading {k+2,k+3}&3 (disjoint); the
// overwrite of stages read last iter is fenced by this iter's syncthreads.
// MODE 0: write fp16 hi/lo split of result. MODE 1: write flip(cos(result)) fp32.
template <int MODE>
__global__ __launch_bounds__(NTHREADS, 2)
void gemm_split2(const __half* __restrict__ Ah, const __half* __restrict__ Al,
                 const __half* __restrict__ B16,
                 const float* __restrict__ bias,
                 float* __restrict__ outF,
                 __half* __restrict__ outH, __half* __restrict__ outL)
{
    extern __shared__ __align__(1024) char smem[];
    const uint32_t sb = smem_u32(smem);

    const int tid = threadIdx.x;
    const int lane = tid & 31;
    const int wid = tid >> 5;
    const int warp_m = wid & 3;       // 4 warps along M, 32 rows each
    const int warp_n = wid >> 2;      // 2 warps along N, 64 cols each
    const int bm = blockIdx.y * BM;
    const int bn = blockIdx.x * BN;

    float acc[2][8][4];
    #pragma unroll
    for (int mt = 0; mt < 2; mt++)
        #pragma unroll
        for (int nt = 0; nt < 8; nt++)
            #pragma unroll
            for (int j = 0; j < 4; j++)
                acc[mt][nt][j] = 0.0f;

    // One chunk's worth of fragment loads + MMAs from stage at sa.
    auto compute_chunk = [&](uint32_t sa) {
        #pragma unroll
        for (int ks = 0; ks < 2; ks++) {
            uint32_t afh[2][4], afl[2][4];
            #pragma unroll
            for (int mt = 0; mt < 2; mt++) {
                const uint32_t row = warp_m * 32 + mt * 16 + (lane & 15);
                const uint32_t seg = ks * 2 + (lane >> 4);
                const uint32_t off = row * 64 + ((seg ^ ((row >> 1) & 3)) << 4);
                ldsm4(afh[mt], sa + OFF_AH + off);
                ldsm4(afl[mt], sa + OFF_AL + off);
            }
            #pragma unroll
            for (int p = 0; p < 4; p++) {
                const uint32_t n = warp_n * 64 + p * 16 + ((lane >> 4) << 3) + (lane & 7);
                const uint32_t seg = ks * 2 + ((lane >> 3) & 1);
                const uint32_t off = n * 64 + ((seg ^ ((n >> 1) & 3)) << 4);
                uint32_t th[4];
                ldsm4(th, sa + OFF_BH + off);
                #pragma unroll
                for (int mt = 0; mt < 2; mt++) {
                    mma16816(acc[mt][2 * p],     afh[mt], th);
                    mma16816(acc[mt][2 * p + 1], afh[mt], th + 2);
                    mma16816(acc[mt][2 * p],     afl[mt], th);
                    mma16816(acc[mt][2 * p + 1], afl[mt], th + 2);
                }
            }
        }
    };

    // Prologue: chunks 0,1 into stages 0,1 (one commit group each)
    load_stage(sb + 0 * STAGE_BYTES, Ah, Al, B16, bm, bn, 0 * BK, tid);
    CP_COMMIT();
    load_stage(sb + 1 * STAGE_BYTES, Ah, Al, B16, bm, bn, 1 * BK, tid);
    CP_COMMIT();

    // 32 iterations x 4 chunks (two phases of 2). All stage offsets literal.
    for (int jj = 0; jj < NCHUNK / 4; jj++) {
        const int k0 = jj * 4;

        // Phase A: compute chunks k0,k0+1 (stages 0,1); load k0+2,k0+3 (stages 2,3)
        CP_WAIT(0);
        __syncthreads();
        load_stage(sb + 2 * STAGE_BYTES, Ah, Al, B16, bm, bn, (k0 + 2) * BK, tid);
        CP_COMMIT();
        load_stage(sb + 3 * STAGE_BYTES, Ah, Al, B16, bm, bn, (k0 + 3) * BK, tid);
        CP_COMMIT();
        compute_chunk(sb + 0 * STAGE_BYTES);
        compute_chunk(sb + 1 * STAGE_BYTES);

        // Phase B: compute chunks k0+2,k0+3 (stages 2,3); load k0+4,k0+5 (stages 0,1)
        CP_WAIT(0);
        __syncthreads();
        if (k0 + 4 < NCHUNK) {
            load_stage(sb + 0 * STAGE_BYTES, Ah, Al, B16, bm, bn, (k0 + 4) * BK, tid);
            CP_COMMIT();
            load_stage(sb + 1 * STAGE_BYTES, Ah, Al, B16, bm, bn, (k0 + 5) * BK, tid);
            CP_COMMIT();
        }
        compute_chunk(sb + 2 * STAGE_BYTES);
        compute_chunk(sb + 3 * STAGE_BYTES);
    }

    // ---------------------------------------------------------------- epilogue
    const int g = lane >> 2;
    const int tig = lane & 3;
    #pragma unroll
    for (int mt = 0; mt < 2; mt++) {
        #pragma unroll
        for (int nt = 0; nt < 8; nt++) {
            const int col = bn + warp_n * 64 + nt * 8 + tig * 2;
            const float2 bv = *reinterpret_cast<const float2*>(bias + col);
            const int r0 = bm + warp_m * 32 + mt * 16 + g;
            const float* a = acc[mt][nt];
            float v00 = a[0] + bv.x, v01 = a[1] + bv.y;   // row r0
            float v10 = a[2] + bv.x, v11 = a[3] + bv.y;   // row r0+8
            if (MODE == 1) {
                float c;
                c = cosf(v00); if (fabsf(c) < 0.01f) c = -c; v00 = c;
                c = cosf(v01); if (fabsf(c) < 0.01f) c = -c; v01 = c;
                c = cosf(v10); if (fabsf(c) < 0.01f) c = -c; v10 = c;
                c = cosf(v11); if (fabsf(c) < 0.01f) c = -c; v11 = c;
                *reinterpret_cast<float2*>(outF + (size_t)r0 * DSIZE + col) =
                    make_float2(v00, v01);
                *reinterpret_cast<float2*>(outF + (size_t)(r0 + 8) * DSIZE + col) =
                    make_float2(v10, v11);
            } else {
                const __half h00 = __float2half_rn(v00), h01 = __float2half_rn(v01);
                const __half h10 = __float2half_rn(v10), h11 = __float2half_rn(v11);
                const __half l00 = __float2half_rn(v00 - __half2float(h00));
                const __half l01 = __float2half_rn(v01 - __half2float(h01));
                const __half l10 = __float2half_rn(v10 - __half2float(h10));
                const __half l11 = __float2half_rn(v11 - __half2float(h11));
                *reinterpret_cast<__half2*>(outH + (size_t)r0 * DSIZE + col) =
                    __halves2half2(h00, h01);
                *reinterpret_cast<__half2*>(outH + (size_t)(r0 + 8) * DSIZE + col) =
                    __halves2half2(h10, h11);
                *reinterpret_cast<__half2*>(outL + (size_t)r0 * DSIZE + col) =
                    __halves2half2(l00, l01);
                *reinterpret_cast<__half2*>(outL + (size_t)(r0 + 8) * DSIZE + col) =
                    __halves2half2(l10, l11);
            }
        }
    }
}

// ---------------------------------------------------------------- fp32 -> fp16 hi/lo
__global__ __launch_bounds__(256)
void split_fp32(const float* __restrict__ in, __half* __restrict__ hi,
                __half* __restrict__ lo)
{
    const size_t i = ((size_t)blockIdx.x * 256 + threadIdx.x) * 4;
    const float4 v = *reinterpret_cast<const float4*>(in + i);
    const __half h0 = __float2half_rn(v.x), h1 = __float2half_rn(v.y);
    const __half h2 = __float2half_rn(v.z), h3 = __float2half_rn(v.w);
    const __half l0 = __float2half_rn(v.x - __half2float(h0));
    const __half l1 = __float2half_rn(v.y - __half2float(h1));
    const __half l2 = __float2half_rn(v.z - __half2float(h2));
    const __half l3 = __float2half_rn(v.w - __half2float(h3));
    reinterpret_cast<__half2*>(hi + i)[0] = __halves2half2(h0, h1);
    reinterpret_cast<__half2*>(hi + i)[1] = __halves2half2(h2, h3);
    reinterpret_cast<__half2*>(lo + i)[0] = __halves2half2(l0, l1);
    reinterpret_cast<__half2*>(lo + i)[1] = __halves2half2(l2, l3);
}

// ---------------------------------------------------------------- fp32 -> fp16 single
__global__ __launch_bounds__(256)
void conv_fp16(const float* __restrict__ in, __half* __restrict__ o)
{
    const size_t i = ((size_t)blockIdx.x * 256 + threadIdx.x) * 4;
    const float4 v = *reinterpret_cast<const float4*>(in + i);
    reinterpret_cast<__half2*>(o + i)[0] =
        __halves2half2(__float2half_rn(v.x), __float2half_rn(v.y));
    reinterpret_cast<__half2*>(o + i)[1] =
        __halves2half2(__float2half_rn(v.z), __float2half_rn(v.w));
}

// ---------------------------------------------------------------- launch
// gemm1 at launch index 3 (ncu capture window lands there).
extern "C" void kernel_launch(void* const* d_in, const int* in_sizes, int n_in,
                              void* d_out, int out_size)
{
    const float* x      = (const float*)d_in[0];
    const float* W      = (const float*)d_in[1];
    const float* b      = (const float*)d_in[2];
    const float* g      = (const float*)d_in[3];
    const float* g_bias = (const float*)d_in[4];
    float* out          = (float*)d_out;

    __half *xh, *xl, *w16, *g16, *hh, *hl;
    cudaGetSymbolAddress((void**)&xh,  g_xh);
    cudaGetSymbolAddress((void**)&xl,  g_xl);
    cudaGetSymbolAddress((void**)&w16, g_w16);
    cudaGetSymbolAddress((void**)&g16, g_g16);
    cudaGetSymbolAddress((void**)&hh,  g_hh);
    cudaGetSymbolAddress((void**)&hl,  g_hl);

    cudaFuncSetAttribute(gemm_split2<0>, cudaFuncAttributeMaxDynamicSharedMemorySize, SMEM_TOTAL);
    cudaFuncSetAttribute(gemm_split2<1>, cudaFuncAttributeMaxDynamicSharedMemorySize, SMEM_TOTAL);

    const int sgrid = (int)(NELEM / 4 / 256);        // 16384
    const dim3 ggrid(DSIZE / BN, DSIZE / BM);        // (32, 32)

    split_fp32<<<sgrid, 256>>>(x, xh, xl);                            // 0
    conv_fp16<<<sgrid, 256>>>(W, w16);                                // 1
    conv_fp16<<<sgrid, 256>>>(g, g16);                                // 2
    // h = x @ W^T + b, written as fp16 hi/lo split
    gemm_split2<0><<<ggrid, NTHREADS, SMEM_TOTAL>>>(xh, xl, w16, b,
                                                    nullptr, hh, hl); // 3 <- profiled
    // out = flip(cos(h @ g^T + g_bias))
    gemm_split2<1><<<ggrid, NTHREADS, SMEM_TOTAL>>>(hh, hl, g16, g_bias,
                                                    out, nullptr, nullptr); // 4
}